// round 1
// baseline (speedup 1.0000x reference)
#include <cuda_runtime.h>
#include <cuda_bf16.h>

#define MULTW 4
#define HID 4096
#define MH 16384           // MULT * HIDDEN
#define TOK_PER_CTA 4
#define NT 512
#define NWARP (NT / 32)
// smem: 4 tokens of bf16 x (128 KB) + reduction scratch + weights
#define SMEM_BYTES (TOK_PER_CTA * MH * 2 + (NWARP * 20 + 16) * 4)

// fn transposed: fnT[j] = (fn[0][j], fn[1][j], fn[2][j], fn[3][j])
__device__ float4 g_fnT[MH];

__global__ void prep_fnT(const float* __restrict__ fn) {
    int j = blockIdx.x * blockDim.x + threadIdx.x;
    if (j < MH)
        g_fnT[j] = make_float4(fn[j], fn[MH + j], fn[2 * MH + j], fn[3 * MH + j]);
}

__device__ __forceinline__ float2 bf2f2(unsigned u) {
    __nv_bfloat162 b = *reinterpret_cast<const __nv_bfloat162*>(&u);
    return __bfloat1622float2(b);
}

__global__ __launch_bounds__(NT, 1) void hchead_kernel(
    const float* __restrict__ x,
    const float* __restrict__ scale,
    const float* __restrict__ base,
    float* __restrict__ out)
{
    extern __shared__ __align__(16) unsigned char smem[];
    __nv_bfloat16* xs = reinterpret_cast<__nv_bfloat16*>(smem);
    float* red = reinterpret_cast<float*>(smem + TOK_PER_CTA * MH * 2);
    float* wsh = red + NWARP * 20;

    const int tid = threadIdx.x;
    const size_t tok0 = (size_t)blockIdx.x * TOK_PER_CTA;

    // acc layout: t*5 + 0 = sum(x^2),  t*5 + 1+m = dot with fn[m]
    float acc[20];
#pragma unroll
    for (int i = 0; i < 20; i++) acc[i] = 0.f;

    // ------- Phase 1: load x, bf16-round, stash in smem, accumulate sums -------
#pragma unroll
    for (int k = 0; k < MH / 4 / NT; k++) {   // 8 iterations
        const int f = tid + k * NT;           // float4 index (j = 4f)
        const float4 fn0 = g_fnT[4 * f + 0];
        const float4 fn1 = g_fnT[4 * f + 1];
        const float4 fn2 = g_fnT[4 * f + 2];
        const float4 fn3 = g_fnT[4 * f + 3];
#pragma unroll
        for (int t = 0; t < TOK_PER_CTA; t++) {
            float4 v = reinterpret_cast<const float4*>(x + (tok0 + t) * MH)[f];
            __nv_bfloat162 b0 = __floats2bfloat162_rn(v.x, v.y);
            __nv_bfloat162 b1 = __floats2bfloat162_rn(v.z, v.w);
            uint2 st;
            st.x = *reinterpret_cast<unsigned*>(&b0);
            st.y = *reinterpret_cast<unsigned*>(&b1);
            reinterpret_cast<uint2*>(xs + t * MH)[f] = st;
            float x0 = __bfloat162float(b0.x), x1 = __bfloat162float(b0.y);
            float x2 = __bfloat162float(b1.x), x3 = __bfloat162float(b1.y);
            acc[t * 5 + 0] += x0 * x0 + x1 * x1 + x2 * x2 + x3 * x3;
            acc[t * 5 + 1] += x0 * fn0.x + x1 * fn1.x + x2 * fn2.x + x3 * fn3.x;
            acc[t * 5 + 2] += x0 * fn0.y + x1 * fn1.y + x2 * fn2.y + x3 * fn3.y;
            acc[t * 5 + 3] += x0 * fn0.z + x1 * fn1.z + x2 * fn2.z + x3 * fn3.z;
            acc[t * 5 + 4] += x0 * fn0.w + x1 * fn1.w + x2 * fn2.w + x3 * fn3.w;
        }
    }

    // ------- Block reduction of 20 partials -------
#pragma unroll
    for (int i = 0; i < 20; i++) {
#pragma unroll
        for (int o = 16; o > 0; o >>= 1)
            acc[i] += __shfl_xor_sync(0xffffffffu, acc[i], o);
    }
    const int warp = tid >> 5, lane = tid & 31;
    if (lane == 0) {
#pragma unroll
        for (int i = 0; i < 20; i++) red[warp * 20 + i] = acc[i];
    }
    __syncthreads();

    if (tid < TOK_PER_CTA) {
        const int t = tid;
        float ss = 0.f, d0 = 0.f, d1 = 0.f, d2 = 0.f, d3 = 0.f;
        for (int w = 0; w < NWARP; w++) {
            ss += red[w * 20 + t * 5 + 0];
            d0 += red[w * 20 + t * 5 + 1];
            d1 += red[w * 20 + t * 5 + 2];
            d2 += red[w * 20 + t * 5 + 3];
            d3 += red[w * 20 + t * 5 + 4];
        }
        const float rms = sqrtf(ss * (1.0f / MH) + 1e-6f);
        const float inv = 1.0f / rms;
        const float s = scale[0];
        const float a0 = s * (d0 * inv) + base[0];
        const float a1 = s * (d1 * inv) + base[1];
        const float a2 = s * (d2 * inv) + base[2];
        const float a3 = s * (d3 * inv) + base[3];
        const float idn = 1.0f / (fabsf(a0) + fabsf(a1) + fabsf(a2) + fabsf(a3) + 1e-6f);
        wsh[t * 4 + 0] = a0 * idn;
        wsh[t * 4 + 1] = a1 * idn;
        wsh[t * 4 + 2] = a2 * idn;
        wsh[t * 4 + 3] = a3 * idn;
    }
    __syncthreads();

    // ------- Phase 2: y[t][h] = sum_m w[t][m] * xf[t][m*HID + h] -------
#pragma unroll
    for (int t = 0; t < TOK_PER_CTA; t++) {
        const float w0 = wsh[t * 4 + 0], w1 = wsh[t * 4 + 1];
        const float w2 = wsh[t * 4 + 2], w3 = wsh[t * 4 + 3];
        const int h0 = tid * 8;   // 8 outputs per thread (4096 / 512)
        const __nv_bfloat16* bp = xs + t * MH;
        uint4 u0 = *reinterpret_cast<const uint4*>(bp + 0 * HID + h0);
        uint4 u1 = *reinterpret_cast<const uint4*>(bp + 1 * HID + h0);
        uint4 u2 = *reinterpret_cast<const uint4*>(bp + 2 * HID + h0);
        uint4 u3 = *reinterpret_cast<const uint4*>(bp + 3 * HID + h0);

        float r[8];
        float2 p;
        p = bf2f2(u0.x); r[0] = w0 * p.x; r[1] = w0 * p.y;
        p = bf2f2(u0.y); r[2] = w0 * p.x; r[3] = w0 * p.y;
        p = bf2f2(u0.z); r[4] = w0 * p.x; r[5] = w0 * p.y;
        p = bf2f2(u0.w); r[6] = w0 * p.x; r[7] = w0 * p.y;

        p = bf2f2(u1.x); r[0] += w1 * p.x; r[1] += w1 * p.y;
        p = bf2f2(u1.y); r[2] += w1 * p.x; r[3] += w1 * p.y;
        p = bf2f2(u1.z); r[4] += w1 * p.x; r[5] += w1 * p.y;
        p = bf2f2(u1.w); r[6] += w1 * p.x; r[7] += w1 * p.y;

        p = bf2f2(u2.x); r[0] += w2 * p.x; r[1] += w2 * p.y;
        p = bf2f2(u2.y); r[2] += w2 * p.x; r[3] += w2 * p.y;
        p = bf2f2(u2.z); r[4] += w2 * p.x; r[5] += w2 * p.y;
        p = bf2f2(u2.w); r[6] += w2 * p.x; r[7] += w2 * p.y;

        p = bf2f2(u3.x); r[0] += w3 * p.x; r[1] += w3 * p.y;
        p = bf2f2(u3.y); r[2] += w3 * p.x; r[3] += w3 * p.y;
        p = bf2f2(u3.z); r[4] += w3 * p.x; r[5] += w3 * p.y;
        p = bf2f2(u3.w); r[6] += w3 * p.x; r[7] += w3 * p.y;

        float4* op = reinterpret_cast<float4*>(out + (tok0 + t) * HID + h0);
        op[0] = make_float4(r[0], r[1], r[2], r[3]);
        op[1] = make_float4(r[4], r[5], r[6], r[7]);
    }
}

extern "C" void kernel_launch(void* const* d_in, const int* in_sizes, int n_in,
                              void* d_out, int out_size) {
    const float* x     = (const float*)d_in[0];   // [T, 4*4096] fp32
    const float* fn    = (const float*)d_in[1];   // [4, 16384]  fp32
    const float* scale = (const float*)d_in[2];   // [1]
    const float* base  = (const float*)d_in[3];   // [4]
    float* out = (float*)d_out;                   // [T, 4096] fp32

    const int T = in_sizes[0] / MH;               // 8192
    prep_fnT<<<(MH + 255) / 256, 256>>>(fn);

    cudaFuncSetAttribute(hchead_kernel,
                         cudaFuncAttributeMaxDynamicSharedMemorySize, SMEM_BYTES);
    hchead_kernel<<<T / TOK_PER_CTA, NT, SMEM_BYTES>>>(x, scale, base, out);
}